// round 4
// baseline (speedup 1.0000x reference)
#include <cuda_runtime.h>

// ---------------------------------------------------------------------------
// Problem constants (fixed shapes per reference)
// ---------------------------------------------------------------------------
constexpr int HD   = 128;      // hidden dim
constexpr int H4   = 32;       // HD / 4 (float4 lanes)
constexpr int NS   = 5000;
constexpr int NM   = 100000;
constexpr int NR   = 2000;
constexpr int ESM  = 2000000;
constexpr int ERM  = 1000000;
constexpr int ESIM = 2000000;
constexpr int LBL  = 500000;

// ---------------------------------------------------------------------------
// Device scratch (static: allocation-free kernel_launch)
// ---------------------------------------------------------------------------
__device__ float g_xm[2][(size_t)NM * HD];   // m features, ping-pong (layer0 -> slot0, layer1 -> slot1)
__device__ float g_xs[2][(size_t)NS * HD];
__device__ float g_xr[2][(size_t)NR * HD];
__device__ float g_xw0[(size_t)NM * HD];     // (x_m @ gcnW0) * dinv0
__device__ float g_xw1[(size_t)NM * HD];     // (x_m @ gcnW1) * dinv1
__device__ float g_ys[(size_t)NS * HD];      // x_s @ sageWl[l,0]
__device__ float g_yr[(size_t)NR * HD];      // x_r @ sageWl[l,2]
__device__ float g_tmp_s[(size_t)NS * HD];   // x_s @ sageWr[l,1]
__device__ float g_tmp_r[(size_t)NR * HD];   // x_r @ sageWr[l,3]
__device__ float g_wrsum[HD * HD];           // Wr[l,0] + Wr[l,2]
__device__ float g_ball[HD];                 // bl[l,0]+bl[l,2]+gcn_b[l,0]+gcn_b[l,1]

__device__ int   g_c_sm_m[NM];   // #sm edges per dst (m)
__device__ int   g_c_rm_m[NM];
__device__ int   g_c_sim_d[NM];  // #sim edges per dst
__device__ int   g_c_sim_s[NM];  // #sim edges per src
__device__ int   g_c_sm_s[NS];   // #sm edges per src (s)
__device__ int   g_c_rm_r[NR];

__device__ float g_invc_sm[NM];  // 1/max(cnt,1) for sm->m mean
__device__ float g_invc_rm[NM];
__device__ float g_dinv0[NM];    // rsqrt(deg) for gcn fwd (deg = cnt_dst+1)
__device__ float g_dinv1[NM];    // rsqrt(deg) for gcn rev
__device__ float g_invc_s[NS];
__device__ float g_invc_r[NR];

// ---------------------------------------------------------------------------
// Small helper kernels
// ---------------------------------------------------------------------------
__global__ void hist_k(const int* __restrict__ idx, int n, int* __restrict__ cnt) {
    int i = blockIdx.x * blockDim.x + threadIdx.x;
    if (i < n) atomicAdd(&cnt[idx[i]], 1);
}

__global__ void invc_k(const int* __restrict__ cnt, float* __restrict__ o, int n) {
    int i = blockIdx.x * blockDim.x + threadIdx.x;
    if (i < n) o[i] = 1.0f / fmaxf((float)cnt[i], 1.0f);
}

__global__ void dinv_k(const int* __restrict__ cnt, float* __restrict__ o, int n) {
    int i = blockIdx.x * blockDim.x + threadIdx.x;
    if (i < n) o[i] = rsqrtf((float)(cnt[i] + 1));  // deg includes self loop, always > 0
}

__global__ void relu_k(float* __restrict__ x, int n) {
    int i = blockIdx.x * blockDim.x + threadIdx.x;
    if (i < n) x[i] = fmaxf(x[i], 0.0f);
}

__global__ void prep_k(const float* __restrict__ Wr0, const float* __restrict__ Wr2,
                       float* __restrict__ Wsum,
                       const float* __restrict__ b0, const float* __restrict__ b2,
                       const float* __restrict__ gb0, const float* __restrict__ gb1,
                       float* __restrict__ ball) {
    int i = blockIdx.x * blockDim.x + threadIdx.x;
    if (i < HD * HD) Wsum[i] = Wr0[i] + Wr2[i];
    if (i < HD)      ball[i] = b0[i] + b2[i] + gb0[i] + gb1[i];
}

// ---------------------------------------------------------------------------
// GEMM: OUT[nrows,128] = f( (xscale * X) @ W ) with fused epilogue.
//   OUT = (X .* xscale[i]) @ W  + bias + s1[i]*add1[i,:] + s2[i]*add2[i,:]
//   then OUT *= oscale[i]; then relu.
// W is [128,128] row-major (k-major). Tile: 64 rows x 128 cols per block,
// 256 threads, W + X tile staged in 96KB dynamic SMEM, 2 CTAs/SM.
// FFMA-bound by design: per k4 step a warp does 12 LDS.128 vs 128 FFMA inst.
// ---------------------------------------------------------------------------
#define FMA4(A, S, Wv) { (A).x = fmaf((S), (Wv).x, (A).x); (A).y = fmaf((S), (Wv).y, (A).y); \
                         (A).z = fmaf((S), (Wv).z, (A).z); (A).w = fmaf((S), (Wv).w, (A).w); }

__global__ __launch_bounds__(256, 2)
void gemm128_ep(const float* __restrict__ X, const float* __restrict__ W,
                float* __restrict__ OUT, int nrows,
                const float* __restrict__ xscale, const float* __restrict__ oscale,
                const float* __restrict__ bias,
                const float* __restrict__ add1, const float* __restrict__ s1,
                const float* __restrict__ add2, const float* __restrict__ s2,
                int do_relu)
{
    extern __shared__ float4 smem[];
    float4* sW = smem;            // 128*32 float4 = 64KB
    float4* sX = smem + HD * H4;  //  64*32 float4 = 32KB

    const int tid  = threadIdx.x;
    const int row0 = blockIdx.x * 64;

    const float4* W4 = reinterpret_cast<const float4*>(W);
#pragma unroll
    for (int i = 0; i < 16; i++) sW[tid + i * 256] = W4[tid + i * 256];

    const float4* X4 = reinterpret_cast<const float4*>(X);
#pragma unroll
    for (int i = 0; i < 8; i++) {
        int f  = tid + i * 256;
        int r  = f >> 5;
        int gr = row0 + r;
        float4 v = make_float4(0.f, 0.f, 0.f, 0.f);
        if (gr < nrows) {
            v = X4[(size_t)gr * H4 + (f & 31)];
            if (xscale) { float s = xscale[gr]; v.x *= s; v.y *= s; v.z *= s; v.w *= s; }
        }
        sX[f] = v;
    }
    __syncthreads();

    const int lane  = tid & 31;
    const int rbase = (tid >> 5) * 8;

    float4 acc[8];
#pragma unroll
    for (int r = 0; r < 8; r++) acc[r] = make_float4(0.f, 0.f, 0.f, 0.f);

    for (int k4 = 0; k4 < 32; k4++) {
        float4 w0 = sW[(4 * k4 + 0) * H4 + lane];
        float4 w1 = sW[(4 * k4 + 1) * H4 + lane];
        float4 w2 = sW[(4 * k4 + 2) * H4 + lane];
        float4 w3 = sW[(4 * k4 + 3) * H4 + lane];
#pragma unroll
        for (int r = 0; r < 8; r++) {
            float4 xv = sX[(rbase + r) * H4 + k4];   // broadcast within warp
            FMA4(acc[r], xv.x, w0);
            FMA4(acc[r], xv.y, w1);
            FMA4(acc[r], xv.z, w2);
            FMA4(acc[r], xv.w, w3);
        }
    }

    float4 bv = make_float4(0.f, 0.f, 0.f, 0.f);
    if (bias) bv = reinterpret_cast<const float4*>(bias)[lane];

#pragma unroll
    for (int r = 0; r < 8; r++) {
        int gr = row0 + rbase + r;
        if (gr >= nrows) break;
        float4 o = acc[r];
        o.x += bv.x; o.y += bv.y; o.z += bv.z; o.w += bv.w;
        if (add1) {
            float s = s1 ? s1[gr] : 1.0f;
            float4 a = reinterpret_cast<const float4*>(add1)[(size_t)gr * H4 + lane];
            o.x = fmaf(a.x, s, o.x); o.y = fmaf(a.y, s, o.y);
            o.z = fmaf(a.z, s, o.z); o.w = fmaf(a.w, s, o.w);
        }
        if (add2) {
            float s = s2 ? s2[gr] : 1.0f;
            float4 a = reinterpret_cast<const float4*>(add2)[(size_t)gr * H4 + lane];
            o.x = fmaf(a.x, s, o.x); o.y = fmaf(a.y, s, o.y);
            o.z = fmaf(a.z, s, o.z); o.w = fmaf(a.w, s, o.w);
        }
        if (oscale) { float s = oscale[gr]; o.x *= s; o.y *= s; o.z *= s; o.w *= s; }
        if (do_relu) {
            o.x = fmaxf(o.x, 0.f); o.y = fmaxf(o.y, 0.f);
            o.z = fmaxf(o.z, 0.f); o.w = fmaxf(o.w, 0.f);
        }
        reinterpret_cast<float4*>(OUT)[(size_t)gr * H4 + lane] = o;
    }
}

// ---------------------------------------------------------------------------
// Edge scatter: warp per edge; lane = one float4 of the 128-wide row.
//   acc[sidx[e], :] += feat[gidx[e], :] * (dscale ? dscale[sidx[e]] : 1)
// Vector RED (red.global.add.v4.f32) — 4x fewer L2 atomic ops than scalar.
// ---------------------------------------------------------------------------
__device__ __forceinline__ void red_add4(float4* addr, float4 v) {
    asm volatile("red.global.add.v4.f32 [%0], {%1, %2, %3, %4};"
                 :: "l"(addr), "f"(v.x), "f"(v.y), "f"(v.z), "f"(v.w) : "memory");
}

__global__ void scatter_k(const float4* __restrict__ feat, float4* __restrict__ acc,
                          const int* __restrict__ gidx, const int* __restrict__ sidx,
                          const float* __restrict__ dscale, int E)
{
    int wid = (blockIdx.x * blockDim.x + threadIdx.x) >> 5;
    if (wid >= E) return;
    int lane = threadIdx.x & 31;
    int g = __ldg(&gidx[wid]);
    int d = __ldg(&sidx[wid]);
    float4 v = feat[(size_t)g * H4 + lane];
    if (dscale) {
        float s = __ldg(&dscale[d]);
        v.x *= s; v.y *= s; v.z *= s; v.w *= s;
    }
    red_add4(&acc[(size_t)d * H4 + lane], v);
}

// ---------------------------------------------------------------------------
// Final predictions: warp per label pair, two 128-d dots sharing the m row.
//   out[j]       = dot(x_s[lbl_s[j]], x_m[lbl_m[j]])
//   out[LBL + j] = dot(x_r[lbl_r[j]], x_m[lbl_m[j]])
// ---------------------------------------------------------------------------
__global__ void predict_k(const float4* __restrict__ xs, const float4* __restrict__ xm,
                          const float4* __restrict__ xr,
                          const int* __restrict__ ls, const int* __restrict__ lm,
                          const int* __restrict__ lr, float* __restrict__ out)
{
    int wid = (blockIdx.x * blockDim.x + threadIdx.x) >> 5;
    if (wid >= LBL) return;
    int lane = threadIdx.x & 31;
    int im = __ldg(&lm[wid]);
    int is = __ldg(&ls[wid]);
    int ir = __ldg(&lr[wid]);
    float4 m = xm[(size_t)im * H4 + lane];
    float4 s = xs[(size_t)is * H4 + lane];
    float4 r = xr[(size_t)ir * H4 + lane];
    float d1 = m.x * s.x + m.y * s.y + m.z * s.z + m.w * s.w;
    float d2 = m.x * r.x + m.y * r.y + m.z * r.z + m.w * r.w;
#pragma unroll
    for (int o = 16; o > 0; o >>= 1) {
        d1 += __shfl_xor_sync(0xffffffffu, d1, o);
        d2 += __shfl_xor_sync(0xffffffffu, d2, o);
    }
    if (lane == 0) { out[wid] = d1; out[LBL + wid] = d2; }
}

// ---------------------------------------------------------------------------
// Host orchestration (graph-capturable: kernels + async memsets only)
// ---------------------------------------------------------------------------
#define SYM(p, s) cudaGetSymbolAddress((void**)&(p), s)

extern "C" void kernel_launch(void* const* d_in, const int* in_sizes, int n_in,
                              void* d_out, int out_size)
{
    (void)in_sizes; (void)n_in; (void)out_size;

    const float* emb_s  = (const float*)d_in[0];
    const float* emb_m  = (const float*)d_in[1];
    const float* emb_r  = (const float*)d_in[2];
    const float* sageWl = (const float*)d_in[3];   // [2,4,128,128]
    const float* sageBl = (const float*)d_in[4];   // [2,4,128]
    const float* sageWr = (const float*)d_in[5];   // [2,4,128,128]
    const float* gcnW   = (const float*)d_in[6];   // [2,2,128,128]
    const float* gcnB   = (const float*)d_in[7];   // [2,2,128]
    const int* src_sm   = (const int*)d_in[8];
    const int* dst_sm   = (const int*)d_in[9];
    const int* src_rm   = (const int*)d_in[10];
    const int* dst_rm   = (const int*)d_in[11];
    const int* src_sim  = (const int*)d_in[12];
    const int* dst_sim  = (const int*)d_in[13];
    const int* lbl_s    = (const int*)d_in[14];
    const int* lbl_m    = (const int*)d_in[15];
    const int* lbl_r    = (const int*)d_in[16];
    float* out = (float*)d_out;

    float *xm, *xs, *xr, *xw0, *xw1, *ys, *yr, *tmps, *tmpr, *wrsum, *ball;
    float *invc_sm, *invc_rm, *dinv0, *dinv1, *invc_s, *invc_r;
    int *c_sm_m, *c_rm_m, *c_sim_d, *c_sim_s, *c_sm_s, *c_rm_r;
    SYM(xm, g_xm);   SYM(xs, g_xs);   SYM(xr, g_xr);
    SYM(xw0, g_xw0); SYM(xw1, g_xw1);
    SYM(ys, g_ys);   SYM(yr, g_yr);   SYM(tmps, g_tmp_s); SYM(tmpr, g_tmp_r);
    SYM(wrsum, g_wrsum); SYM(ball, g_ball);
    SYM(invc_sm, g_invc_sm); SYM(invc_rm, g_invc_rm);
    SYM(dinv0, g_dinv0);     SYM(dinv1, g_dinv1);
    SYM(invc_s, g_invc_s);   SYM(invc_r, g_invc_r);
    SYM(c_sm_m, g_c_sm_m);   SYM(c_rm_m, g_c_rm_m);
    SYM(c_sim_d, g_c_sim_d); SYM(c_sim_s, g_c_sim_s);
    SYM(c_sm_s, g_c_sm_s);   SYM(c_rm_r, g_c_rm_r);

    const int SMEM_BYTES = (HD * H4 + 64 * H4) * (int)sizeof(float4);  // 96KB
    cudaFuncSetAttribute(gemm128_ep, cudaFuncAttributeMaxDynamicSharedMemorySize, SMEM_BYTES);

    auto GEMM = [&](const float* X, const float* W, float* O, int nrows,
                    const float* xsc, const float* osc, const float* b,
                    const float* a1, const float* s1, const float* a2, const float* s2, int rl) {
        gemm128_ep<<<(nrows + 63) / 64, 256, SMEM_BYTES>>>(X, W, O, nrows, xsc, osc, b, a1, s1, a2, s2, rl);
    };
    auto SCAT = [&](const float* feat, float* acc, const int* g, const int* s,
                    const float* sc, int E) {
        scatter_k<<<(E + 7) / 8, 256>>>((const float4*)feat, (float4*)acc, g, s, sc, E);
    };

    // ---- degree / count tables (graph is layer-invariant: build once) ----
    cudaMemsetAsync(c_sm_m,  0, NM * sizeof(int));
    cudaMemsetAsync(c_rm_m,  0, NM * sizeof(int));
    cudaMemsetAsync(c_sim_d, 0, NM * sizeof(int));
    cudaMemsetAsync(c_sim_s, 0, NM * sizeof(int));
    cudaMemsetAsync(c_sm_s,  0, NS * sizeof(int));
    cudaMemsetAsync(c_rm_r,  0, NR * sizeof(int));
    hist_k<<<(ESM  + 255) / 256, 256>>>(dst_sm,  ESM,  c_sm_m);
    hist_k<<<(ESM  + 255) / 256, 256>>>(src_sm,  ESM,  c_sm_s);
    hist_k<<<(ERM  + 255) / 256, 256>>>(dst_rm,  ERM,  c_rm_m);
    hist_k<<<(ERM  + 255) / 256, 256>>>(src_rm,  ERM,  c_rm_r);
    hist_k<<<(ESIM + 255) / 256, 256>>>(dst_sim, ESIM, c_sim_d);
    hist_k<<<(ESIM + 255) / 256, 256>>>(src_sim, ESIM, c_sim_s);
    invc_k<<<(NM + 255) / 256, 256>>>(c_sm_m, invc_sm, NM);
    invc_k<<<(NS + 255) / 256, 256>>>(c_sm_s, invc_s,  NS);
    invc_k<<<(NM + 255) / 256, 256>>>(c_rm_m, invc_rm, NM);
    invc_k<<<(NR + 255) / 256, 256>>>(c_rm_r, invc_r,  NR);
    dinv_k<<<(NM + 255) / 256, 256>>>(c_sim_d, dinv0, NM);
    dinv_k<<<(NM + 255) / 256, 256>>>(c_sim_s, dinv1, NM);

    const float* in_m = emb_m;
    const float* in_s = emb_s;
    const float* in_r = emb_r;

    for (int l = 0; l < 2; l++) {
        float* out_m = xm + (size_t)l * NM * HD;
        float* out_s = xs + (size_t)l * NS * HD;
        float* out_r = xr + (size_t)l * NR * HD;

        const float* Wl0 = sageWl + ((size_t)l * 4 + 0) * HD * HD;
        const float* Wl1 = sageWl + ((size_t)l * 4 + 1) * HD * HD;
        const float* Wl2 = sageWl + ((size_t)l * 4 + 2) * HD * HD;
        const float* Wl3 = sageWl + ((size_t)l * 4 + 3) * HD * HD;
        const float* Wr0 = sageWr + ((size_t)l * 4 + 0) * HD * HD;
        const float* Wr1 = sageWr + ((size_t)l * 4 + 1) * HD * HD;
        const float* Wr2 = sageWr + ((size_t)l * 4 + 2) * HD * HD;
        const float* Wr3 = sageWr + ((size_t)l * 4 + 3) * HD * HD;
        const float* bl0 = sageBl + ((size_t)l * 4 + 0) * HD;
        const float* bl1 = sageBl + ((size_t)l * 4 + 1) * HD;
        const float* bl2 = sageBl + ((size_t)l * 4 + 2) * HD;
        const float* bl3 = sageBl + ((size_t)l * 4 + 3) * HD;
        const float* W0  = gcnW + ((size_t)l * 2 + 0) * HD * HD;
        const float* W1  = gcnW + ((size_t)l * 2 + 1) * HD * HD;
        const float* gb0 = gcnB + ((size_t)l * 2 + 0) * HD;
        const float* gb1 = gcnB + ((size_t)l * 2 + 1) * HD;

        // Wr0+Wr2 and summed biases for the m-update
        prep_k<<<64, 256>>>(Wr0, Wr2, wrsum, bl0, bl2, gb0, gb1, ball);

        // xw0 = (x_m @ W0) * dinv0 ; xw1 = (x_m @ W1) * dinv1
        GEMM(in_m, W0, xw0, NM, nullptr, dinv0, nullptr, nullptr, nullptr, nullptr, nullptr, 0);
        GEMM(in_m, W1, xw1, NM, nullptr, dinv1, nullptr, nullptr, nullptr, nullptr, nullptr, 0);
        // acc_m = x_m @ (Wr0+Wr2) + biases + dinv0*xw0 (gcn0 self loop) + dinv1*xw1 (gcn1 self loop)
        GEMM(in_m, wrsum, out_m, NM, nullptr, nullptr, ball, xw0, dinv0, xw1, dinv1, 0);
        // small pre-GEMMs: neighbor features transformed before scatter
        GEMM(in_s, Wl0, ys, NS, nullptr, nullptr, nullptr, nullptr, nullptr, nullptr, nullptr, 0);
        GEMM(in_r, Wl2, yr, NR, nullptr, nullptr, nullptr, nullptr, nullptr, nullptr, nullptr, 0);

        // edge scatters into acc_m (scaled per destination row)
        SCAT(ys,  out_m, src_sm,  dst_sm,  invc_sm, ESM);   // SAGE s->m (mean via invc)
        SCAT(yr,  out_m, src_rm,  dst_rm,  invc_rm, ERM);   // SAGE r->m
        SCAT(xw0, out_m, src_sim, dst_sim, dinv0,   ESIM);  // GCN fwd
        SCAT(xw1, out_m, dst_sim, src_sim, dinv1,   ESIM);  // GCN rev
        relu_k<<<(NM * HD + 255) / 256, 256>>>(out_m, NM * HD);

        // s / r aggregation (aggregate first, tiny GEMM after)
        cudaMemsetAsync(out_s, 0, (size_t)NS * HD * sizeof(float));
        SCAT(in_m, out_s, dst_sm, src_sm, nullptr, ESM);
        cudaMemsetAsync(out_r, 0, (size_t)NR * HD * sizeof(float));
        SCAT(in_m, out_r, dst_rm, src_rm, nullptr, ERM);

        GEMM(in_s,  Wr1, tmps, NS, nullptr, nullptr, nullptr, nullptr, nullptr, nullptr, nullptr, 0);
        GEMM(out_s, Wl1, out_s, NS, invc_s, nullptr, bl1, tmps, nullptr, nullptr, nullptr, 1);
        GEMM(in_r,  Wr3, tmpr, NR, nullptr, nullptr, nullptr, nullptr, nullptr, nullptr, nullptr, 0);
        GEMM(out_r, Wl3, out_r, NR, invc_r, nullptr, bl3, tmpr, nullptr, nullptr, nullptr, 1);

        in_m = out_m; in_s = out_s; in_r = out_r;
    }

    predict_k<<<(LBL + 7) / 8, 256>>>((const float4*)in_s, (const float4*)in_m,
                                      (const float4*)in_r, lbl_s, lbl_m, lbl_r, out);
}

// round 8
// speedup vs baseline: 1.6372x; 1.6372x over previous
#include <cuda_runtime.h>

// ---------------------------------------------------------------------------
// Problem constants (fixed shapes per reference)
// ---------------------------------------------------------------------------
constexpr int HD   = 128;      // hidden dim
constexpr int H4   = 32;       // HD / 4 (float4 lanes)
constexpr int NS   = 5000;
constexpr int NM   = 100000;
constexpr int NR   = 2000;
constexpr int ESM  = 2000000;
constexpr int ERM  = 1000000;
constexpr int ESIM = 2000000;
constexpr int LBL  = 500000;

// ---------------------------------------------------------------------------
// Device scratch (static: allocation-free kernel_launch)
// ---------------------------------------------------------------------------
__device__ float g_xm[2][(size_t)NM * HD];
__device__ float g_xs[2][(size_t)NS * HD];
__device__ float g_xr[2][(size_t)NR * HD];
__device__ float g_xw0[(size_t)NM * HD];     // (x_m @ gcnW0) * dinv0
__device__ float g_xw1[(size_t)NM * HD];     // (x_m @ gcnW1) * dinv1
__device__ float g_ys[(size_t)NS * HD];      // x_s @ sageWl[l,0]
__device__ float g_yr[(size_t)NR * HD];      // x_r @ sageWl[l,2]
__device__ float g_tmp_s[(size_t)NS * HD];
__device__ float g_tmp_r[(size_t)NR * HD];
__device__ float g_wrsum[HD * HD];
__device__ float g_ball[HD];

// degree / counts
__device__ int   g_c_sm_m[NM];
__device__ int   g_c_rm_m[NM];
__device__ int   g_c_sim_d[NM];
__device__ int   g_c_sim_s[NM];
__device__ int   g_c_sm_s[NS];
__device__ int   g_c_rm_r[NR];
// per-node scales
__device__ float g_invc_sm[NM];
__device__ float g_invc_rm[NM];
__device__ float g_dinv0[NM];
__device__ float g_dinv1[NM];
__device__ float g_invc_s[NS];
__device__ float g_invc_r[NR];
// CSR row pointers + cursors
__device__ int g_rp_sm_m[NM], g_rp_rm_m[NM], g_rp_sim_d[NM], g_rp_sim_s[NM];
__device__ int g_rp_sm_s[NS], g_rp_rm_r[NR];
__device__ int g_cu_sm_m[NM], g_cu_rm_m[NM], g_cu_sim_d[NM], g_cu_sim_s[NM];
__device__ int g_cu_sm_s[NS], g_cu_rm_r[NR];
// CSR adjacency (stores the OTHER endpoint directly = gather index)
__device__ int g_e_sm_m[ESM], g_e_sm_s[ESM];
__device__ int g_e_rm_m[ERM], g_e_rm_r[ERM];
__device__ int g_e_sim_d[ESIM], g_e_sim_s[ESIM];
// scan scratch
__device__ int g_bsum[1024];

// ---------------------------------------------------------------------------
// Small helper kernels
// ---------------------------------------------------------------------------
__global__ void hist2_k(const int* __restrict__ a, int* __restrict__ ca,
                        const int* __restrict__ b, int* __restrict__ cb, int n) {
    int i = blockIdx.x * blockDim.x + threadIdx.x;
    if (i < n) {
        atomicAdd(&ca[a[i]], 1);   // result unused -> REDG
        atomicAdd(&cb[b[i]], 1);
    }
}

__global__ void invc_k(const int* __restrict__ cnt, float* __restrict__ o, int n) {
    int i = blockIdx.x * blockDim.x + threadIdx.x;
    if (i < n) o[i] = 1.0f / fmaxf((float)cnt[i], 1.0f);
}

__global__ void dinv_k(const int* __restrict__ cnt, float* __restrict__ o, int n) {
    int i = blockIdx.x * blockDim.x + threadIdx.x;
    if (i < n) o[i] = rsqrtf((float)(cnt[i] + 1));  // self loop -> deg > 0
}

__global__ void prep_k(const float* __restrict__ Wr0, const float* __restrict__ Wr2,
                       float* __restrict__ Wsum,
                       const float* __restrict__ b0, const float* __restrict__ b2,
                       const float* __restrict__ gb0, const float* __restrict__ gb1,
                       float* __restrict__ ball) {
    int i = blockIdx.x * blockDim.x + threadIdx.x;
    if (i < HD * HD) Wsum[i] = Wr0[i] + Wr2[i];
    if (i < HD)      ball[i] = b0[i] + b2[i] + gb0[i] + gb1[i];
}

// ---- exclusive-scan (3-pass) -------------------------------------------------
__global__ void scan1_k(const int* __restrict__ cnt, int* __restrict__ excl,
                        int* __restrict__ bsum, int n) {
    __shared__ int sm[256];
    int i = blockIdx.x * 256 + threadIdx.x;
    int v = (i < n) ? cnt[i] : 0;
    sm[threadIdx.x] = v; __syncthreads();
    int x = v;
#pragma unroll
    for (int o = 1; o < 256; o <<= 1) {
        int t = (threadIdx.x >= o) ? sm[threadIdx.x - o] : 0;
        __syncthreads();
        x += t; sm[threadIdx.x] = x; __syncthreads();
    }
    if (i < n) excl[i] = x - v;
    if (threadIdx.x == 255) bsum[blockIdx.x] = x;
}

__global__ void scan2_k(int* __restrict__ bsum, int nb) {   // single block, 1024 thr
    __shared__ int sm[1024];
    int t = threadIdx.x;
    int v = (t < nb) ? bsum[t] : 0;
    sm[t] = v; __syncthreads();
    int x = v;
#pragma unroll
    for (int o = 1; o < 1024; o <<= 1) {
        int tv = (t >= o) ? sm[t - o] : 0;
        __syncthreads();
        x += tv; sm[t] = x; __syncthreads();
    }
    if (t < nb) bsum[t] = x - v;
}

__global__ void scan3_k(int* __restrict__ excl, const int* __restrict__ bsum, int n) {
    int i = blockIdx.x * 256 + threadIdx.x;
    if (i < n) excl[i] += bsum[blockIdx.x];
}

// Fused CSR fill: one pass over an edge list builds both direction CSRs.
__global__ void fill2_k(const int* __restrict__ ka, const int* __restrict__ kb,
                        int* __restrict__ cura, int* __restrict__ curb,
                        int* __restrict__ ea, int* __restrict__ eb, int n) {
    int i = blockIdx.x * blockDim.x + threadIdx.x;
    if (i < n) {
        int A = ka[i], B = kb[i];
        ea[atomicAdd(&cura[A], 1)] = B;
        eb[atomicAdd(&curb[B], 1)] = A;
    }
}

// ---------------------------------------------------------------------------
// GEMM: OUT[nrows,128] = f( (xscale * X) @ W ) with fused epilogue (unchanged).
// ---------------------------------------------------------------------------
#define FMA4(A, S, Wv) { (A).x = fmaf((S), (Wv).x, (A).x); (A).y = fmaf((S), (Wv).y, (A).y); \
                         (A).z = fmaf((S), (Wv).z, (A).z); (A).w = fmaf((S), (Wv).w, (A).w); }

__global__ __launch_bounds__(256, 2)
void gemm128_ep(const float* __restrict__ X, const float* __restrict__ W,
                float* __restrict__ OUT, int nrows,
                const float* __restrict__ xscale, const float* __restrict__ oscale,
                const float* __restrict__ bias,
                const float* __restrict__ add1, const float* __restrict__ s1,
                const float* __restrict__ add2, const float* __restrict__ s2,
                int do_relu)
{
    extern __shared__ float4 smem[];
    float4* sW = smem;            // 128*32 float4 = 64KB
    float4* sX = smem + HD * H4;  //  64*32 float4 = 32KB

    const int tid  = threadIdx.x;
    const int row0 = blockIdx.x * 64;

    const float4* W4 = reinterpret_cast<const float4*>(W);
#pragma unroll
    for (int i = 0; i < 16; i++) sW[tid + i * 256] = W4[tid + i * 256];

    const float4* X4 = reinterpret_cast<const float4*>(X);
#pragma unroll
    for (int i = 0; i < 8; i++) {
        int f  = tid + i * 256;
        int r  = f >> 5;
        int gr = row0 + r;
        float4 v = make_float4(0.f, 0.f, 0.f, 0.f);
        if (gr < nrows) {
            v = X4[(size_t)gr * H4 + (f & 31)];
            if (xscale) { float s = xscale[gr]; v.x *= s; v.y *= s; v.z *= s; v.w *= s; }
        }
        sX[f] = v;
    }
    __syncthreads();

    const int lane  = tid & 31;
    const int rbase = (tid >> 5) * 8;

    float4 acc[8];
#pragma unroll
    for (int r = 0; r < 8; r++) acc[r] = make_float4(0.f, 0.f, 0.f, 0.f);

    for (int k4 = 0; k4 < 32; k4++) {
        float4 w0 = sW[(4 * k4 + 0) * H4 + lane];
        float4 w1 = sW[(4 * k4 + 1) * H4 + lane];
        float4 w2 = sW[(4 * k4 + 2) * H4 + lane];
        float4 w3 = sW[(4 * k4 + 3) * H4 + lane];
#pragma unroll
        for (int r = 0; r < 8; r++) {
            float4 xv = sX[(rbase + r) * H4 + k4];
            FMA4(acc[r], xv.x, w0);
            FMA4(acc[r], xv.y, w1);
            FMA4(acc[r], xv.z, w2);
            FMA4(acc[r], xv.w, w3);
        }
    }

    float4 bv = make_float4(0.f, 0.f, 0.f, 0.f);
    if (bias) bv = reinterpret_cast<const float4*>(bias)[lane];

#pragma unroll
    for (int r = 0; r < 8; r++) {
        int gr = row0 + rbase + r;
        if (gr >= nrows) break;
        float4 o = acc[r];
        o.x += bv.x; o.y += bv.y; o.z += bv.z; o.w += bv.w;
        if (add1) {
            float s = s1 ? s1[gr] : 1.0f;
            float4 a = reinterpret_cast<const float4*>(add1)[(size_t)gr * H4 + lane];
            o.x = fmaf(a.x, s, o.x); o.y = fmaf(a.y, s, o.y);
            o.z = fmaf(a.z, s, o.z); o.w = fmaf(a.w, s, o.w);
        }
        if (add2) {
            float s = s2 ? s2[gr] : 1.0f;
            float4 a = reinterpret_cast<const float4*>(add2)[(size_t)gr * H4 + lane];
            o.x = fmaf(a.x, s, o.x); o.y = fmaf(a.y, s, o.y);
            o.z = fmaf(a.z, s, o.z); o.w = fmaf(a.w, s, o.w);
        }
        if (oscale) { float s = oscale[gr]; o.x *= s; o.y *= s; o.z *= s; o.w *= s; }
        if (do_relu) {
            o.x = fmaxf(o.x, 0.f); o.y = fmaxf(o.y, 0.f);
            o.z = fmaxf(o.z, 0.f); o.w = fmaxf(o.w, 0.f);
        }
        reinterpret_cast<float4*>(OUT)[(size_t)gr * H4 + lane] = o;
    }
}

// ---------------------------------------------------------------------------
// Warp-cooperative gather-sum over a CSR row. MLP=4 via independent accumulators.
// ---------------------------------------------------------------------------
__device__ __forceinline__ float4 f4add(float4 a, float4 b) {
    a.x += b.x; a.y += b.y; a.z += b.z; a.w += b.w; return a;
}

__device__ __forceinline__ float4 gsum(const float4* __restrict__ feat,
                                       const int* __restrict__ idx,
                                       int beg, int cnt, int lane) {
    float4 a0 = make_float4(0.f, 0.f, 0.f, 0.f), a1 = a0, a2 = a0, a3 = a0;
    int end = beg + cnt;
    for (int e = beg; e < end; e += 32) {
        int m = min(32, end - e);
        int g = (lane < m) ? __ldg(&idx[e + lane]) : 0;
        int j = 0;
        for (; j + 4 <= m; j += 4) {
            int g0 = __shfl_sync(0xffffffffu, g, j + 0);
            int g1 = __shfl_sync(0xffffffffu, g, j + 1);
            int g2 = __shfl_sync(0xffffffffu, g, j + 2);
            int g3 = __shfl_sync(0xffffffffu, g, j + 3);
            float4 v0 = feat[(size_t)g0 * H4 + lane];
            float4 v1 = feat[(size_t)g1 * H4 + lane];
            float4 v2 = feat[(size_t)g2 * H4 + lane];
            float4 v3 = feat[(size_t)g3 * H4 + lane];
            a0 = f4add(a0, v0); a1 = f4add(a1, v1);
            a2 = f4add(a2, v2); a3 = f4add(a3, v3);
        }
        for (; j < m; j++) {
            int gj = __shfl_sync(0xffffffffu, g, j);
            a0 = f4add(a0, feat[(size_t)gj * H4 + lane]);
        }
    }
    return f4add(f4add(a0, a1), f4add(a2, a3));
}

// Fused m-node update: base (root+bias+self-loops, precomputed by GEMM) +
// four gathered neighbor sums, each with a node-level scale, then relu.
// One read + one write of the 51MB row table instead of 1 read + 7M RED ops.
__global__ void m_update_k(float4* __restrict__ om,
    const float4* __restrict__ ys, const float4* __restrict__ yr,
    const float4* __restrict__ xw0, const float4* __restrict__ xw1,
    const int* __restrict__ rp1, const int* __restrict__ c1, const int* __restrict__ e1,
    const int* __restrict__ rp2, const int* __restrict__ c2, const int* __restrict__ e2,
    const int* __restrict__ rp3, const int* __restrict__ c3, const int* __restrict__ e3,
    const int* __restrict__ rp4, const int* __restrict__ c4, const int* __restrict__ e4,
    const float* __restrict__ s1, const float* __restrict__ s2,
    const float* __restrict__ s3, const float* __restrict__ s4)
{
    int w = (blockIdx.x * blockDim.x + threadIdx.x) >> 5;
    if (w >= NM) return;
    int lane = threadIdx.x & 31;

    float4 o = om[(size_t)w * H4 + lane];
    float4 a; float f;

    a = gsum(ys,  e1, __ldg(&rp1[w]), __ldg(&c1[w]), lane); f = __ldg(&s1[w]); FMA4(o, f, a);
    a = gsum(yr,  e2, __ldg(&rp2[w]), __ldg(&c2[w]), lane); f = __ldg(&s2[w]); FMA4(o, f, a);
    a = gsum(xw0, e3, __ldg(&rp3[w]), __ldg(&c3[w]), lane); f = __ldg(&s3[w]); FMA4(o, f, a);
    a = gsum(xw1, e4, __ldg(&rp4[w]), __ldg(&c4[w]), lane); f = __ldg(&s4[w]); FMA4(o, f, a);

    o.x = fmaxf(o.x, 0.f); o.y = fmaxf(o.y, 0.f);
    o.z = fmaxf(o.z, 0.f); o.w = fmaxf(o.w, 0.f);
    om[(size_t)w * H4 + lane] = o;
}

// s/r aggregation: raw neighbor sum (mean scale folded into following GEMM).
__global__ void agg_k(const float4* __restrict__ feat, float4* __restrict__ out,
                      const int* __restrict__ rp, const int* __restrict__ cnt,
                      const int* __restrict__ eidx, int n)
{
    int w = (blockIdx.x * blockDim.x + threadIdx.x) >> 5;
    if (w >= n) return;
    int lane = threadIdx.x & 31;
    out[(size_t)w * H4 + lane] = gsum(feat, eidx, __ldg(&rp[w]), __ldg(&cnt[w]), lane);
}

// ---------------------------------------------------------------------------
// Final predictions: warp per label pair, two 128-d dots sharing the m row.
// ---------------------------------------------------------------------------
__global__ void predict_k(const float4* __restrict__ xs, const float4* __restrict__ xm,
                          const float4* __restrict__ xr,
                          const int* __restrict__ ls, const int* __restrict__ lm,
                          const int* __restrict__ lr, float* __restrict__ out)
{
    int wid = (blockIdx.x * blockDim.x + threadIdx.x) >> 5;
    if (wid >= LBL) return;
    int lane = threadIdx.x & 31;
    int im = __ldg(&lm[wid]);
    int is = __ldg(&ls[wid]);
    int ir = __ldg(&lr[wid]);
    float4 m = xm[(size_t)im * H4 + lane];
    float4 s = xs[(size_t)is * H4 + lane];
    float4 r = xr[(size_t)ir * H4 + lane];
    float d1 = m.x * s.x + m.y * s.y + m.z * s.z + m.w * s.w;
    float d2 = m.x * r.x + m.y * r.y + m.z * r.z + m.w * r.w;
#pragma unroll
    for (int o = 16; o > 0; o >>= 1) {
        d1 += __shfl_xor_sync(0xffffffffu, d1, o);
        d2 += __shfl_xor_sync(0xffffffffu, d2, o);
    }
    if (lane == 0) { out[wid] = d1; out[LBL + wid] = d2; }
}

// ---------------------------------------------------------------------------
// Host orchestration (graph-capturable: kernels + async D2D copies only)
// ---------------------------------------------------------------------------
#define SYM(p, s) cudaGetSymbolAddress((void**)&(p), s)

extern "C" void kernel_launch(void* const* d_in, const int* in_sizes, int n_in,
                              void* d_out, int out_size)
{
    (void)in_sizes; (void)n_in; (void)out_size;

    const float* emb_s  = (const float*)d_in[0];
    const float* emb_m  = (const float*)d_in[1];
    const float* emb_r  = (const float*)d_in[2];
    const float* sageWl = (const float*)d_in[3];
    const float* sageBl = (const float*)d_in[4];
    const float* sageWr = (const float*)d_in[5];
    const float* gcnW   = (const float*)d_in[6];
    const float* gcnB   = (const float*)d_in[7];
    const int* src_sm   = (const int*)d_in[8];
    const int* dst_sm   = (const int*)d_in[9];
    const int* src_rm   = (const int*)d_in[10];
    const int* dst_rm   = (const int*)d_in[11];
    const int* src_sim  = (const int*)d_in[12];
    const int* dst_sim  = (const int*)d_in[13];
    const int* lbl_s    = (const int*)d_in[14];
    const int* lbl_m    = (const int*)d_in[15];
    const int* lbl_r    = (const int*)d_in[16];
    float* out = (float*)d_out;

    float *xm, *xs, *xr, *xw0, *xw1, *ys, *yr, *tmps, *tmpr, *wrsum, *ball;
    float *invc_sm, *invc_rm, *dinv0, *dinv1, *invc_s, *invc_r;
    int *c_sm_m, *c_rm_m, *c_sim_d, *c_sim_s, *c_sm_s, *c_rm_r;
    int *rp_sm_m, *rp_rm_m, *rp_sim_d, *rp_sim_s, *rp_sm_s, *rp_rm_r;
    int *cu_sm_m, *cu_rm_m, *cu_sim_d, *cu_sim_s, *cu_sm_s, *cu_rm_r;
    int *e_sm_m, *e_sm_s, *e_rm_m, *e_rm_r, *e_sim_d, *e_sim_s, *bsum;
    SYM(xm, g_xm);   SYM(xs, g_xs);   SYM(xr, g_xr);
    SYM(xw0, g_xw0); SYM(xw1, g_xw1);
    SYM(ys, g_ys);   SYM(yr, g_yr);   SYM(tmps, g_tmp_s); SYM(tmpr, g_tmp_r);
    SYM(wrsum, g_wrsum); SYM(ball, g_ball);
    SYM(invc_sm, g_invc_sm); SYM(invc_rm, g_invc_rm);
    SYM(dinv0, g_dinv0);     SYM(dinv1, g_dinv1);
    SYM(invc_s, g_invc_s);   SYM(invc_r, g_invc_r);
    SYM(c_sm_m, g_c_sm_m);   SYM(c_rm_m, g_c_rm_m);
    SYM(c_sim_d, g_c_sim_d); SYM(c_sim_s, g_c_sim_s);
    SYM(c_sm_s, g_c_sm_s);   SYM(c_rm_r, g_c_rm_r);
    SYM(rp_sm_m, g_rp_sm_m); SYM(rp_rm_m, g_rp_rm_m);
    SYM(rp_sim_d, g_rp_sim_d); SYM(rp_sim_s, g_rp_sim_s);
    SYM(rp_sm_s, g_rp_sm_s); SYM(rp_rm_r, g_rp_rm_r);
    SYM(cu_sm_m, g_cu_sm_m); SYM(cu_rm_m, g_cu_rm_m);
    SYM(cu_sim_d, g_cu_sim_d); SYM(cu_sim_s, g_cu_sim_s);
    SYM(cu_sm_s, g_cu_sm_s); SYM(cu_rm_r, g_cu_rm_r);
    SYM(e_sm_m, g_e_sm_m); SYM(e_sm_s, g_e_sm_s);
    SYM(e_rm_m, g_e_rm_m); SYM(e_rm_r, g_e_rm_r);
    SYM(e_sim_d, g_e_sim_d); SYM(e_sim_s, g_e_sim_s);
    SYM(bsum, g_bsum);

    const int SMEM_BYTES = (HD * H4 + 64 * H4) * (int)sizeof(float4);  // 96KB
    cudaFuncSetAttribute(gemm128_ep, cudaFuncAttributeMaxDynamicSharedMemorySize, SMEM_BYTES);

    auto GEMM = [&](const float* X, const float* W, float* O, int nrows,
                    const float* xsc, const float* osc, const float* b,
                    const float* a1, const float* s1, const float* a2, const float* s2, int rl) {
        gemm128_ep<<<(nrows + 63) / 64, 256, SMEM_BYTES>>>(X, W, O, nrows, xsc, osc, b, a1, s1, a2, s2, rl);
    };
    auto SCAN = [&](const int* cnt, int* rp, int n) {
        int nb = (n + 255) / 256;
        scan1_k<<<nb, 256>>>(cnt, rp, bsum, n);
        scan2_k<<<1, 1024>>>(bsum, nb);
        scan3_k<<<nb, 256>>>(rp, bsum, n);
    };

    // ---- degree / count tables ----
    cudaMemsetAsync(c_sm_m,  0, NM * sizeof(int));
    cudaMemsetAsync(c_rm_m,  0, NM * sizeof(int));
    cudaMemsetAsync(c_sim_d, 0, NM * sizeof(int));
    cudaMemsetAsync(c_sim_s, 0, NM * sizeof(int));
    cudaMemsetAsync(c_sm_s,  0, NS * sizeof(int));
    cudaMemsetAsync(c_rm_r,  0, NR * sizeof(int));
    hist2_k<<<(ESM  + 255) / 256, 256>>>(dst_sm,  c_sm_m,  src_sm,  c_sm_s,  ESM);
    hist2_k<<<(ERM  + 255) / 256, 256>>>(dst_rm,  c_rm_m,  src_rm,  c_rm_r,  ERM);
    hist2_k<<<(ESIM + 255) / 256, 256>>>(dst_sim, c_sim_d, src_sim, c_sim_s, ESIM);
    invc_k<<<(NM + 255) / 256, 256>>>(c_sm_m, invc_sm, NM);
    invc_k<<<(NS + 255) / 256, 256>>>(c_sm_s, invc_s,  NS);
    invc_k<<<(NM + 255) / 256, 256>>>(c_rm_m, invc_rm, NM);
    invc_k<<<(NR + 255) / 256, 256>>>(c_rm_r, invc_r,  NR);
    dinv_k<<<(NM + 255) / 256, 256>>>(c_sim_d, dinv0, NM);
    dinv_k<<<(NM + 255) / 256, 256>>>(c_sim_s, dinv1, NM);

    // ---- CSR build (graph is layer-invariant) ----
    SCAN(c_sm_m,  rp_sm_m,  NM);
    SCAN(c_rm_m,  rp_rm_m,  NM);
    SCAN(c_sim_d, rp_sim_d, NM);
    SCAN(c_sim_s, rp_sim_s, NM);
    SCAN(c_sm_s,  rp_sm_s,  NS);
    SCAN(c_rm_r,  rp_rm_r,  NR);
    cudaMemcpyAsync(cu_sm_m,  rp_sm_m,  NM * sizeof(int), cudaMemcpyDeviceToDevice);
    cudaMemcpyAsync(cu_rm_m,  rp_rm_m,  NM * sizeof(int), cudaMemcpyDeviceToDevice);
    cudaMemcpyAsync(cu_sim_d, rp_sim_d, NM * sizeof(int), cudaMemcpyDeviceToDevice);
    cudaMemcpyAsync(cu_sim_s, rp_sim_s, NM * sizeof(int), cudaMemcpyDeviceToDevice);
    cudaMemcpyAsync(cu_sm_s,  rp_sm_s,  NS * sizeof(int), cudaMemcpyDeviceToDevice);
    cudaMemcpyAsync(cu_rm_r,  rp_rm_r,  NR * sizeof(int), cudaMemcpyDeviceToDevice);
    fill2_k<<<(ESM  + 255) / 256, 256>>>(dst_sm,  src_sm,  cu_sm_m,  cu_sm_s,  e_sm_m,  e_sm_s,  ESM);
    fill2_k<<<(ERM  + 255) / 256, 256>>>(dst_rm,  src_rm,  cu_rm_m,  cu_rm_r,  e_rm_m,  e_rm_r,  ERM);
    fill2_k<<<(ESIM + 255) / 256, 256>>>(dst_sim, src_sim, cu_sim_d, cu_sim_s, e_sim_d, e_sim_s, ESIM);

    const float* in_m = emb_m;
    const float* in_s = emb_s;
    const float* in_r = emb_r;

    for (int l = 0; l < 2; l++) {
        float* out_m = xm + (size_t)l * NM * HD;
        float* out_s = xs + (size_t)l * NS * HD;
        float* out_r = xr + (size_t)l * NR * HD;

        const float* Wl0 = sageWl + ((size_t)l * 4 + 0) * HD * HD;
        const float* Wl1 = sageWl + ((size_t)l * 4 + 1) * HD * HD;
        const float* Wl2 = sageWl + ((size_t)l * 4 + 2) * HD * HD;
        const float* Wl3 = sageWl + ((size_t)l * 4 + 3) * HD * HD;
        const float* Wr0 = sageWr + ((size_t)l * 4 + 0) * HD * HD;
        const float* Wr1 = sageWr + ((size_t)l * 4 + 1) * HD * HD;
        const float* Wr2 = sageWr + ((size_t)l * 4 + 2) * HD * HD;
        const float* Wr3 = sageWr + ((size_t)l * 4 + 3) * HD * HD;
        const float* bl0 = sageBl + ((size_t)l * 4 + 0) * HD;
        const float* bl1 = sageBl + ((size_t)l * 4 + 1) * HD;
        const float* bl2 = sageBl + ((size_t)l * 4 + 2) * HD;
        const float* bl3 = sageBl + ((size_t)l * 4 + 3) * HD;
        const float* W0  = gcnW + ((size_t)l * 2 + 0) * HD * HD;
        const float* W1  = gcnW + ((size_t)l * 2 + 1) * HD * HD;
        const float* gb0 = gcnB + ((size_t)l * 2 + 0) * HD;
        const float* gb1 = gcnB + ((size_t)l * 2 + 1) * HD;

        prep_k<<<64, 256>>>(Wr0, Wr2, wrsum, bl0, bl2, gb0, gb1, ball);

        // s/r aggregation first (reads previous-layer m): raw sums, mean via GEMM xscale
        agg_k<<<(NS * 32 + 255) / 256, 256>>>((const float4*)in_m, (float4*)out_s,
                                              rp_sm_s, c_sm_s, e_sm_s, NS);
        agg_k<<<(NR * 32 + 255) / 256, 256>>>((const float4*)in_m, (float4*)out_r,
                                              rp_rm_r, c_rm_r, e_rm_r, NR);

        // xw0 = (x_m @ W0) * dinv0 ; xw1 = (x_m @ W1) * dinv1
        GEMM(in_m, W0, xw0, NM, nullptr, dinv0, nullptr, nullptr, nullptr, nullptr, nullptr, 0);
        GEMM(in_m, W1, xw1, NM, nullptr, dinv1, nullptr, nullptr, nullptr, nullptr, nullptr, 0);
        // base: x_m @ (Wr0+Wr2) + biases + self-loop terms
        GEMM(in_m, wrsum, out_m, NM, nullptr, nullptr, ball, xw0, dinv0, xw1, dinv1, 0);
        // neighbor features pre-transformed (tiny GEMMs)
        GEMM(in_s, Wl0, ys, NS, nullptr, nullptr, nullptr, nullptr, nullptr, nullptr, nullptr, 0);
        GEMM(in_r, Wl2, yr, NR, nullptr, nullptr, nullptr, nullptr, nullptr, nullptr, nullptr, 0);

        // fused gather-update of all m nodes (replaces 4 atomic scatters + relu)
        m_update_k<<<(NM * 32 + 255) / 256, 256>>>((float4*)out_m,
            (const float4*)ys, (const float4*)yr, (const float4*)xw0, (const float4*)xw1,
            rp_sm_m,  c_sm_m,  e_sm_m,
            rp_rm_m,  c_rm_m,  e_rm_m,
            rp_sim_d, c_sim_d, e_sim_d,
            rp_sim_s, c_sim_s, e_sim_s,
            invc_sm, invc_rm, dinv0, dinv1);

        // s / r linear layers (mean via xscale) + relu
        GEMM(in_s,  Wr1, tmps, NS, nullptr, nullptr, nullptr, nullptr, nullptr, nullptr, nullptr, 0);
        GEMM(out_s, Wl1, out_s, NS, invc_s, nullptr, bl1, tmps, nullptr, nullptr, nullptr, 1);
        GEMM(in_r,  Wr3, tmpr, NR, nullptr, nullptr, nullptr, nullptr, nullptr, nullptr, nullptr, 0);
        GEMM(out_r, Wl3, out_r, NR, invc_r, nullptr, bl3, tmpr, nullptr, nullptr, nullptr, 1);

        in_m = out_m; in_s = out_s; in_r = out_r;
    }

    predict_k<<<(LBL + 7) / 8, 256>>>((const float4*)in_s, (const float4*)in_m,
                                      (const float4*)in_r, lbl_s, lbl_m, lbl_r, out);
}